// round 10
// baseline (speedup 1.0000x reference)
#include <cuda_runtime.h>

// BottomUp_57131654972209: adding-doubling radiative transfer, v4.
// a,r,t,s : (E,60,48) fp32 -> flux_up, flux_down, absorbed : (E,59,48).
//
// One CTA (384 thr) per TWO atmospheres (96 columns). Each thread owns an
// ADJACENT column pair (2g, 2g+1) x ~8 layers -> all smem traffic is LDS.64/
// STS.64 (conflict-free), all output traffic is direct sector-aligned STG.64.
// rs per segment via contracting 12-layer halo descent (threads j>=5 exact).
// Upward/downward fluxes are exact affine shfl scans (width 8).
// A is never staged: read once from global in down-emit (LDG.64).
// Divisions avoided via bounded series for 1/(1-tmp^2), tmp = rs*r <= ~0.21.

#define LAY   60
#define LM1   59
#define NC    48
#define BLK   384
#define PITCH 100
#define BUFN  6024          // swz(59,95)+1

__device__ __forceinline__ int swz(int l, int c) {
    return l * PITCH + ((l >> 3) << 2) + c;
}
__device__ __forceinline__ float inv3(float u) {   // 1/(1-u), 0<=u<~0.09
    return fmaf(u, fmaf(u, fmaf(u, fmaf(u, 1.0f, 1.0f), 1.0f), 1.0f), 1.0f);
}

__global__ void __launch_bounds__(BLK, 2)
adk(const float* __restrict__ A, const float* __restrict__ R,
    const float* __restrict__ T, const float* __restrict__ S,
    float* __restrict__ Fup, float* __restrict__ Fdn, float* __restrict__ Abs)
{
    extern __shared__ float sm[];
    float* Rs = sm;
    float* Ts = Rs + BUFN;
    float* Ss = Ts + BUFN;

    const int  tid = threadIdx.x;
    const long e0  = (long)blockIdx.x * 2;
    const long ib2 = e0 * 1440;                  // float2 base into inputs

    const float2* R2 = (const float2*)R;
    const float2* T2 = (const float2*)T;
    const float2* S2 = (const float2*)S;
    const float2* A2 = (const float2*)A;
    float2* Fup2 = (float2*)Fup;
    float2* Fdn2 = (float2*)Fdn;
    float2* Abs2 = (float2*)Abs;

    // ---- stage R,T,S: 2880 float2 per array, coalesced ----
    #pragma unroll
    for (int k = 0; k < 8; ++k) {
        int p = tid + k * BLK;
        if (p < 2880) {
            int atm = p / 1440;
            int rem = p - atm * 1440;
            int l   = rem / 24;
            int c2  = rem - l * 24;
            int d   = l * PITCH + ((l >> 3) << 2) + atm * NC + 2 * c2;
            *(float2*)&Rs[d] = R2[ib2 + p];
            *(float2*)&Ts[d] = T2[ib2 + p];
            *(float2*)&Ss[d] = S2[ib2 + p];
        }
    }
    __syncthreads();

    const int j   = tid & 7;            // segment index
    const int gg  = tid >> 3;           // pair index 0..47
    const int cc  = 2 * gg;             // smem column of pair
    const int atm = gg / 24;            // which atmosphere
    const int nv  = (j == 7) ? 3 : 8;
    const int hi  = j * 8 + nv - 1;
    const int base = j * 804 + cc;      // swz(8j, cc)

    // per-thread global float2 offsets (column pair, layer stride 24)
    const long ain = ib2 + (long)atm * 1440 + (gg - atm * 24) + 192 * j;
    const long oo  = (e0 + atm) * 1416 + (gg - atm * 24) + 192 * j;

    // ---- rs via halo descent (j>=5 exact from layer 59; j<=4 seeded) ----
    float x0, x1;
    int l0;
    if (j >= 5) {
        float2 rr = *(const float2*)&Rs[swz(59, cc)];
        float2 tt = *(const float2*)&Ts[swz(59, cc)];
        x0 = fmaf(rr.x * tt.x, tt.x, rr.x) * inv3(rr.x * rr.x);
        x1 = fmaf(rr.y * tt.y, tt.y, rr.y) * inv3(rr.y * rr.y);
        l0 = 58;
    } else {
        x0 = 0.18f; x1 = 0.18f;          // seed; error decays ~0.17^12
        l0 = hi + 12;
    }
    for (int l = l0; l > hi; --l) {
        int d = swz(l, cc);
        float2 rr = *(const float2*)&Rs[d];
        float2 tt = *(const float2*)&Ts[d];
        float p0 = x0 * rr.x, p1 = x1 * rr.y;
        x0 = fmaf(x0, tt.x * tt.x, rr.x) * ((1.0f + p0) * inv3(p0 * p0));
        x1 = fmaf(x1, tt.y * tt.y, rr.y) * ((1.0f + p1) * inv3(p1 * p1));
    }

    // ---- owned descent: rsv + upward (ss,kk); build both affine maps ----
    float rsv0[8], rsv1[8], ssu0[8], ssu1[8], kku0[8], kku1[8];
    float amU0 = 1.f, abU0 = 0.f, amU1 = 1.f, abU1 = 0.f;
    float amD0 = 1.f, abD0 = 0.f, amD1 = 1.f, abD1 = 0.f;
    float2 snv = *(const float2*)&Ss[swz(hi + 1, cc)];
    float sn0 = snv.x, sn1 = snv.y;
    #pragma unroll
    for (int i = 7; i >= 0; --i) {
        if (i < nv) {
            int d0 = base + PITCH * i;
            float2 rr = *(const float2*)&Rs[d0];
            float2 tt = *(const float2*)&Ts[d0];
            float2 ssv = *(const float2*)&Ss[d0];
            float s1a = sn0; sn0 = ssv.x;
            float s1b = sn1; sn1 = ssv.y;
            {   // col 0
                float rv  = x0;            rsv0[i] = rv;
                float tmp = rv * rr.x;
                float iv  = inv3(tmp * tmp);
                float i1p = (1.0f - tmp) * iv;
                float i1m = (1.0f + tmp) * iv;
                float sU  = fmaf(s1a, fmaf(tmp, i1p, 1.0f), ssv.x * rv * i1p);
                float kU  = tt.x * i1m;
                ssu0[i] = sU; kku0[i] = kU;
                amU0 = kU * amU0;
                abU0 = kU * (abU0 + sU);
                float sD  = fmaf(ssv.x, fmaf(tmp, i1m, 1.0f), s1a * rr.x * i1m);
                float kD  = tt.x * i1p;
                float w   = amD0 * kD;
                abD0 = fmaf(w, sD, abD0);
                amD0 = w;
                x0 = fmaf(rv, tt.x * tt.x, rr.x) * i1m;
            }
            {   // col 1
                float rv  = x1;            rsv1[i] = rv;
                float tmp = rv * rr.y;
                float iv  = inv3(tmp * tmp);
                float i1p = (1.0f - tmp) * iv;
                float i1m = (1.0f + tmp) * iv;
                float sU  = fmaf(s1b, fmaf(tmp, i1p, 1.0f), ssv.y * rv * i1p);
                float kU  = tt.y * i1m;
                ssu1[i] = sU; kku1[i] = kU;
                amU1 = kU * amU1;
                abU1 = kU * (abU1 + sU);
                float sD  = fmaf(ssv.y, fmaf(tmp, i1m, 1.0f), s1b * rr.y * i1m);
                float kD  = tt.y * i1p;
                float w   = amD1 * kD;
                abD1 = fmaf(w, sD, abD1);
                amD1 = w;
                x1 = fmaf(rv, tt.y * tt.y, rr.y) * i1m;
            }
        }
    }

    // ---- upward suffix scan + downward prefix scan (affine, width 8) ----
    #pragma unroll
    for (int d = 1; d < 8; d <<= 1) {
        float fm0 = __shfl_down_sync(0xffffffffu, amU0, d, 8);
        float fb0 = __shfl_down_sync(0xffffffffu, abU0, d, 8);
        float fm1 = __shfl_down_sync(0xffffffffu, amU1, d, 8);
        float fb1 = __shfl_down_sync(0xffffffffu, abU1, d, 8);
        float gm0 = __shfl_up_sync  (0xffffffffu, amD0, d, 8);
        float gb0 = __shfl_up_sync  (0xffffffffu, abD0, d, 8);
        float gm1 = __shfl_up_sync  (0xffffffffu, amD1, d, 8);
        float gb1 = __shfl_up_sync  (0xffffffffu, abD1, d, 8);
        if (j + d < 8) {
            abU0 = fmaf(amU0, fb0, abU0); amU0 *= fm0;
            abU1 = fmaf(amU1, fb1, abU1); amU1 *= fm1;
        }
        if (j >= d) {
            abD0 = fmaf(amD0, gb0, abD0); amD0 *= gm0;
            abD1 = fmaf(amD1, gb1, abD1); amD1 *= gm1;
        }
    }
    float cu0 = __shfl_down_sync(0xffffffffu, abU0, 1, 8);
    float cu1 = __shfl_down_sync(0xffffffffu, abU1, 1, 8);
    float cd0 = __shfl_up_sync  (0xffffffffu, abD0, 1, 8);
    float cd1 = __shfl_up_sync  (0xffffffffu, abD1, 1, 8);
    cu0 = (j == 7) ? 0.0f : cu0;
    cu1 = (j == 7) ? 0.0f : cu1;
    cd0 = (j == 0) ? 0.0f : cd0;
    cd1 = (j == 0) ? 0.0f : cd1;

    // ---- up-emit (descending): STG flux_up; stash fu over ssu ----
    #pragma unroll
    for (int i = 7; i >= 0; --i) {
        if (i < nv) {
            float fu0 = cu0 + ssu0[i];
            float fu1 = cu1 + ssu1[i];
            cu0 = fu0 * kku0[i];
            cu1 = fu1 * kku1[i];
            Fup2[oo + 24 * i] = make_float2(fu0, fu1);
            ssu0[i] = fu0; ssu1[i] = fu1;    // fuv
        }
    }

    // ---- down-emit (ascending): STG flux_down + absorbed ----
    float2 scv = *(const float2*)&Ss[base];     // s[lo]
    float sc0 = scv.x, sc1 = scv.y;
    #pragma unroll
    for (int i = 0; i < 8; ++i) {
        if (i < nv) {
            int d0 = base + PITCH * i;
            float2 rr = *(const float2*)&Rs[d0];
            float2 tt = *(const float2*)&Ts[d0];
            float2 s1v = *(const float2*)&Ss[swz(8 * j + i + 1, cc)];
            float2 aa = A2[ain + 24 * i];
            float fd0, fd1, ab0, ab1;
            {   // col 0
                float rv  = rsv0[i];
                float tmp = rv * rr.x;
                float iv  = inv3(tmp * tmp);
                float i1p = (1.0f - tmp) * iv;
                float i1m = (1.0f + tmp) * iv;
                float sD  = fmaf(sc0, fmaf(tmp, i1m, 1.0f), s1v.x * rr.x * i1m);
                float ww  = fmaf(tt.x * rv, i1p, 1.0f);
                fd0 = cd0 + sD;
                ab0 = aa.x * fmaf(ww, fd0, ssu0[i]);
                cd0 = fd0 * (tt.x * i1p);
                sc0 = s1v.x;
            }
            {   // col 1
                float rv  = rsv1[i];
                float tmp = rv * rr.y;
                float iv  = inv3(tmp * tmp);
                float i1p = (1.0f - tmp) * iv;
                float i1m = (1.0f + tmp) * iv;
                float sD  = fmaf(sc1, fmaf(tmp, i1m, 1.0f), s1v.y * rr.y * i1m);
                float ww  = fmaf(tt.y * rv, i1p, 1.0f);
                fd1 = cd1 + sD;
                ab1 = aa.y * fmaf(ww, fd1, ssu1[i]);
                cd1 = fd1 * (tt.y * i1p);
                sc1 = s1v.y;
            }
            Fdn2[oo + 24 * i] = make_float2(fd0, fd1);
            Abs2[oo + 24 * i] = make_float2(ab0, ab1);
        }
    }
}

extern "C" void kernel_launch(void* const* d_in, const int* in_sizes, int n_in,
                              void* d_out, int out_size)
{
    const float* A = (const float*)d_in[0];
    const float* R = (const float*)d_in[1];
    const float* T = (const float*)d_in[2];
    const float* S = (const float*)d_in[3];

    const int total = in_sizes[0];            // E * 60 * 48
    const int E     = total / (LAY * NC);     // 8192 (even)
    const int nper  = E * LM1 * NC;

    float* out  = (float*)d_out;
    float* fup  = out;
    float* fdn  = out + nper;
    float* absd = out + 2 * nper;

    const int smem_bytes = 3 * BUFN * (int)sizeof(float);   // 72,288 B
    cudaFuncSetAttribute(adk, cudaFuncAttributeMaxDynamicSharedMemorySize, smem_bytes);
    adk<<<E / 2, BLK, smem_bytes>>>(A, R, T, S, fup, fdn, absd);
}